// round 16
// baseline (speedup 1.0000x reference)
#include <cuda_runtime.h>

// Problem shape (fixed by the dataset)
#define BATCH 8
#define CH    256
#define HH    128
#define WW    128
#define HO    64
#define WO    64
#define NPLANES 2048

// Dynamic smem layout. Pair-packed log table, row- and col-padded:
//   lt[129][65] of float2:  lt[r+1][k+1] = { log2(relu(col 2k)),
//                                            log2(relu(col 2k+1)) } (input row r)
//   Table row 0 (= input row -1) is -inf; col j=0 .y (= input col -1) is -inf.
//   Window taps for wo at table row tr: lt[tr][wo].y (col 2wo-1),
//   lt[tr][wo+1].x (2wo), lt[tr][wo+1].y (2wo+1). Out-of-range taps give
//   ex2(-inf) = 0 automatically.
//   sc[48] : [0..15] warp max partials, [32] invm, [33..41] w1 raw
#define LT_OFF 0
#define SC_OFF (129 * 65 * 2)
#define SMEM_FLOATS (SC_OFF + 48)
#define SMEM_BYTES  (SMEM_FLOATS * 4)

#define NINF __int_as_float(0xff800000)

__device__ __forceinline__ float f_lg2(float x) {
    float y; asm("lg2.approx.f32 %0, %1;" : "=f"(y) : "f"(x)); return y;
}
__device__ __forceinline__ float f_ex2(float x) {
    float y; asm("ex2.approx.f32 %0, %1;" : "=f"(y) : "f"(x)); return y;
}
__device__ __forceinline__ float f_rcp(float x) {
    float y; asm("rcp.approx.f32 %0, %1;" : "=f"(y) : "f"(x)); return y;
}

// One block = one (b,c) plane. 512 threads = (64, 8), 3 blocks/SM (42 regs).
// Phase 1: stream plane once (incremental addressing, STS.64 pair stores),
//          build padded log table + plane max.
// Phase 2: thread (tx,ty) -> wo=tx, ho=8ty..8ty+7; carried-row reuse with the
//          top-row conv contribution pre-dotted into one scalar.
__global__ __launch_bounds__(512, 3) void fused_ppool_kernel(
    const float* __restrict__ bottom,
    const float* __restrict__ w1,
    const float* __restrict__ a1,
    const float* __restrict__ w2,
    const float* __restrict__ b2,
    float* __restrict__ out_res,
    float* __restrict__ out_p)
{
    extern __shared__ float smem[];
    float2* lt = (float2*)(smem + LT_OFF);
    float*  sc = smem + SC_OFF;

    const int plane = blockIdx.x;
    const int c = plane & (CH - 1);
    const float* __restrict__ src = bottom + (size_t)plane * (HH * WW);

    const int tx = threadIdx.x;          // 0..63 -> wo
    const int ty = threadIdx.y;          // 0..7
    const int t  = ty * 64 + tx;         // 0..511
    const int wid = t >> 5, lid = t & 31;

    if (t < 9) sc[33 + t] = __ldg(&w1[c * 9 + t]);
    // -inf pads: table row 0 (j=0..64); col j=0 for rows 1..128
    if (t < 65)              lt[t] = make_float2(NINF, NINF);
    if (t >= 65 && t < 193)  lt[(t - 64) * 65] = make_float2(NINF, NINF);

    // ---- Phase 1: stream plane, pair-packed log table + |x| max ----
    // Thread owns col pair k=t&63; rows r0, r0+8, ..., r0+120 (r0 = t>>6).
    float mx = 0.f;
    {
        const int k  = t & 63;
        const int r0 = t >> 6;
        const float2* gp = (const float2*)src + r0 * 64 + k;
        float2*       sp = lt + (r0 + 1) * 65 + (k + 1);
        #pragma unroll
        for (int i = 0; i < 16; i++) {
            float2 v = __ldg(gp);
            *sp = make_float2(f_lg2(fmaxf(v.x, 0.f)),    // lg2(0) = -inf
                              f_lg2(fmaxf(v.y, 0.f)));
            mx = fmaxf(mx, fmaxf(fabsf(v.x), fabsf(v.y)));
            gp += 8 * 64;
            sp += 8 * 65;
        }
    }
    #pragma unroll
    for (int o = 16; o; o >>= 1) mx = fmaxf(mx, __shfl_xor_sync(0xffffffffu, mx, o));
    if (lid == 0) sc[wid] = mx;
    __syncthreads();
    if (t < 16) {
        float m = sc[t];
        #pragma unroll
        for (int o = 8; o; o >>= 1) m = fmaxf(m, __shfl_xor_sync(0xffffu, m, o));
        if (t == 0) sc[32] = 1.0f / (m + 1.0f);
    }
    __syncthreads();

    // Fold 1/m into register weights (conv(x/m) = conv_{w/m}(x)).
    const float invm = sc[32];
    float w[9];
    #pragma unroll
    for (int i = 0; i < 9; i++) w[i] = sc[33 + i] * invm;
    const float av = __ldg(&a1[c]);
    const float wv = __ldg(&w2[c]);
    const float bv = __ldg(&b2[c]);

    // ---- Phase 2: 8 vertically-adjacent outputs, carried-row reuse ----
    const int ho0 = ty * 8;

    // Carried top row: conv contribution pre-dotted (input row 2*ho0-1),
    // log taps from padded table row 2*ho0.
    float atop, ea;
    float2 qa;
    {
        const float* srowt = src + (2 * ho0 - 1) * WW + 2 * tx;
        bool rv = (ho0 > 0);
        float am = (rv && tx > 0) ? __ldg(srowt - 1) : 0.f;
        float2 q = rv ? __ldg((const float2*)srowt) : make_float2(0.f, 0.f);
        atop = w[0] * am;
        atop = fmaf(w[1], q.x, atop);
        atop = fmaf(w[2], q.y, atop);
        const float2* lt0 = lt + (2 * ho0) * 65 + tx;
        ea = lt0[0].y;           // col 2tx-1
        qa = lt0[1];             // cols 2tx, 2tx+1
    }

    const float*  srow = src + (2 * ho0) * WW + 2 * tx;   // mid row of 1st win
    const float2* ltr  = lt + (2 * ho0 + 1) * 65 + tx;    // row b of 1st win
    size_t o = ((size_t)plane * HO + ho0) * WO + tx;

    #pragma unroll
    for (int g = 0; g < 8; g++) {
        // Raw rows 2ho (mid) and 2ho+1 (bottom) — always valid rows 0..127.
        float  bm = (tx > 0) ? __ldg(srow - 1) : 0.f;
        float2 bq = __ldg((const float2*)srow);
        float  cm = (tx > 0) ? __ldg(srow + WW - 1) : 0.f;
        float2 cq = __ldg((const float2*)(srow + WW));
        // Log taps rows b (2ho+1) and c (2ho+2).
        float  eb = ltr[0].y;
        float2 qb = ltr[1];
        float  ec = ltr[65].y;
        float2 qc = ltr[66];

        // Depthwise conv: carried top dot + mid/bottom rows.
        float conv = atop;
        conv = fmaf(w[3], bm,   conv);
        conv = fmaf(w[4], bq.x, conv);
        conv = fmaf(w[5], bq.y, conv);
        conv = fmaf(w[6], cm,   conv);
        conv = fmaf(w[7], cq.x, conv);
        conv = fmaf(w[8], cq.y, conv);

        // Pre-dot next window's top row (= this bottom row).
        atop = w[0] * cm;
        atop = fmaf(w[1], cq.x, atop);
        atop = fmaf(w[2], cq.y, atop);

        // PReLU + affine + clamp -> exponent p
        float x = conv > 0.f ? conv : av * conv;
        float p = fminf(fmaxf(fmaf(x, wv, bv), 1.0f), 110.0f);

        // Power-mean over the 3x3 window (tree-summed ex2 burst).
        float t0 = f_ex2(p * ea)   + f_ex2(p * qa.x);
        float t1 = f_ex2(p * qa.y) + f_ex2(p * eb);
        float t2 = f_ex2(p * qb.x) + f_ex2(p * qb.y);
        float t3 = f_ex2(p * ec)   + f_ex2(p * qc.x);
        float sum = ((t0 + t1) + (t2 + t3)) + f_ex2(p * qc.y);

        float mean = fmaf(sum, (1.0f / 9.0f), 1e-12f);
        float res  = f_ex2(f_lg2(mean) * f_rcp(p));

        out_res[o] = res;
        out_p[o]   = p;

        // Shift: bottom row logs become next top row logs.
        ea = ec; qa = qc;
        srow += 2 * WW;
        ltr  += 2 * 65;
        o += WO;
    }
}

extern "C" void kernel_launch(void* const* d_in, const int* in_sizes, int n_in,
                              void* d_out, int out_size) {
    const float* bottom = (const float*)d_in[0];
    const float* w1     = (const float*)d_in[1];
    const float* a1     = (const float*)d_in[2];
    const float* w2     = (const float*)d_in[3];
    const float* b2     = (const float*)d_in[4];
    float* out = (float*)d_out;
    const size_t N = (size_t)BATCH * CH * HO * WO;   // elements per output tensor

    cudaFuncSetAttribute(fused_ppool_kernel,
                         cudaFuncAttributeMaxDynamicSharedMemorySize, SMEM_BYTES);

    dim3 blk(64, 8);
    fused_ppool_kernel<<<NPLANES, blk, SMEM_BYTES>>>(bottom, w1, a1, w2, b2,
                                                     out, out + N);

    (void)in_sizes; (void)n_in; (void)out_size;
}

// round 17
// speedup vs baseline: 1.0175x; 1.0175x over previous
#include <cuda_runtime.h>

// Problem shape (fixed by the dataset)
#define BATCH 8
#define CH    256
#define HH    128
#define WW    128
#define HO    64
#define WO    64
#define NPLANES 2048

// Dynamic smem layout. Pair-packed log table, row- and col-padded:
//   lt[129][65] of float2:  lt[r+1][k+1] = { log2(relu(col 2k)),
//                                            log2(relu(col 2k+1)) } (input row r)
//   Table row 0 (= input row -1) is -inf; col j=0 (= input col -1 in .y) is
//   -inf. Window taps for wo at table row tr: lt[tr][wo].y (col 2wo-1),
//   lt[tr][wo+1].x (2wo), lt[tr][wo+1].y (2wo+1). Out-of-range taps give
//   ex2(-inf) = 0 automatically.
//   sc[56] : [0..31] warp max partials, [32] invm, [33..41] w1 raw,
//            [42..50] folded weights w1[i]*invm
#define LT_OFF 0
#define SC_OFF (129 * 65 * 2)
#define SMEM_FLOATS (SC_OFF + 56)
#define SMEM_BYTES  (SMEM_FLOATS * 4)

#define NINF __int_as_float(0xff800000)

__device__ __forceinline__ float f_lg2(float x) {
    float y; asm("lg2.approx.f32 %0, %1;" : "=f"(y) : "f"(x)); return y;
}
__device__ __forceinline__ float f_ex2(float x) {
    float y; asm("ex2.approx.f32 %0, %1;" : "=f"(y) : "f"(x)); return y;
}
__device__ __forceinline__ float f_rcp(float x) {
    float y; asm("rcp.approx.f32 %0, %1;" : "=f"(y) : "f"(x)); return y;
}

// One block = one (b,c) plane. 1024 threads = (64, 16), 2 blocks/SM (64 warps,
// 32 regs). Weights kept in smem (broadcast LDS) to fit the 32-reg cap.
// Phase 1: stream plane once, pair-packed padded log table + plane max.
// Phase 2: thread (tx,ty) -> wo=tx, ho=4ty..4ty+3; carried-row reuse with the
//          top-row conv contribution pre-dotted into one scalar.
__global__ __launch_bounds__(1024, 2) void fused_ppool_kernel(
    const float* __restrict__ bottom,
    const float* __restrict__ w1,
    const float* __restrict__ a1,
    const float* __restrict__ w2,
    const float* __restrict__ b2,
    float* __restrict__ out_res,
    float* __restrict__ out_p)
{
    extern __shared__ float smem[];
    float2* lt = (float2*)(smem + LT_OFF);
    float*  sc = smem + SC_OFF;

    const int plane = blockIdx.x;
    const int c = plane & (CH - 1);
    const float* __restrict__ src = bottom + (size_t)plane * (HH * WW);

    const int tx = threadIdx.x;          // 0..63 -> wo
    const int ty = threadIdx.y;          // 0..15
    const int t  = ty * 64 + tx;         // 0..1023
    const int wid = t >> 5, lid = t & 31;

    if (t < 9) sc[33 + t] = __ldg(&w1[c * 9 + t]);
    // -inf pads: table row 0 (j=0..64); col j=0 for rows 1..128
    if (t < 65)              lt[t] = make_float2(NINF, NINF);
    if (t >= 65 && t < 193)  lt[(t - 64) * 65] = make_float2(NINF, NINF);

    // ---- Phase 1: stream plane, pair-packed log table + |x| max ----
    // Thread owns col pair k=t&63; rows r0, r0+16, ..., r0+112 (r0 = t>>6).
    float mx = 0.f;
    {
        const int k  = t & 63;
        const int r0 = t >> 6;           // 0..15
        const float2* gp = (const float2*)src + r0 * 64 + k;
        float2*       sp = lt + (r0 + 1) * 65 + (k + 1);
        #pragma unroll
        for (int i = 0; i < 8; i++) {
            float2 v = __ldg(gp);
            *sp = make_float2(f_lg2(fmaxf(v.x, 0.f)),    // lg2(0) = -inf
                              f_lg2(fmaxf(v.y, 0.f)));
            mx = fmaxf(mx, fmaxf(fabsf(v.x), fabsf(v.y)));
            gp += 16 * 64;
            sp += 16 * 65;
        }
    }
    #pragma unroll
    for (int o = 16; o; o >>= 1) mx = fmaxf(mx, __shfl_xor_sync(0xffffffffu, mx, o));
    if (lid == 0) sc[wid] = mx;
    __syncthreads();
    if (t < 32) {
        float m = sc[t];
        #pragma unroll
        for (int o = 16; o; o >>= 1) m = fmaxf(m, __shfl_xor_sync(0xffffffffu, m, o));
        if (t == 0) sc[32] = 1.0f / (m + 1.0f);
    }
    __syncthreads();
    // Fold 1/m into smem weights (conv(x/m) = conv_{w/m}(x)); smem residency
    // keeps them out of the 32-reg budget.
    if (t < 9) sc[42 + t] = sc[33 + t] * sc[32];
    __syncthreads();

    const float av = __ldg(&a1[c]);
    const float wv = __ldg(&w2[c]);
    const float bv = __ldg(&b2[c]);

    // ---- Phase 2: 4 vertically-adjacent outputs, carried-row reuse ----
    const int ho0 = ty * 4;

    // Carried top row: conv contribution pre-dotted (input row 2*ho0-1),
    // log taps from padded table row 2*ho0.
    float atop, ea;
    float2 qa;
    {
        const float* srowt = src + (2 * ho0 - 1) * WW + 2 * tx;
        bool rv = (ho0 > 0);
        float am = (rv && tx > 0) ? __ldg(srowt - 1) : 0.f;
        float2 q = rv ? __ldg((const float2*)srowt) : make_float2(0.f, 0.f);
        atop = sc[42] * am;
        atop = fmaf(sc[43], q.x, atop);
        atop = fmaf(sc[44], q.y, atop);
        const float2* lt0 = lt + (2 * ho0) * 65 + tx;
        ea = lt0[0].y;           // col 2tx-1
        qa = lt0[1];             // cols 2tx, 2tx+1
    }

    const float*  srow = src + (2 * ho0) * WW + 2 * tx;   // mid row of 1st win
    const float2* ltr  = lt + (2 * ho0 + 1) * 65 + tx;    // row b of 1st win
    size_t o = ((size_t)plane * HO + ho0) * WO + tx;

    #pragma unroll
    for (int g = 0; g < 4; g++) {
        // Raw rows 2ho (mid) and 2ho+1 (bottom) — always valid rows 0..127.
        float  bm = (tx > 0) ? __ldg(srow - 1) : 0.f;
        float2 bq = __ldg((const float2*)srow);
        float  cm = (tx > 0) ? __ldg(srow + WW - 1) : 0.f;
        float2 cq = __ldg((const float2*)(srow + WW));
        // Log taps rows b (2ho+1) and c (2ho+2).
        float  eb = ltr[0].y;
        float2 qb = ltr[1];
        float  ec = ltr[65].y;
        float2 qc = ltr[66];

        // Depthwise conv: carried top dot + mid/bottom rows (smem weights).
        float conv = atop;
        conv = fmaf(sc[45], bm,   conv);
        conv = fmaf(sc[46], bq.x, conv);
        conv = fmaf(sc[47], bq.y, conv);
        conv = fmaf(sc[48], cm,   conv);
        conv = fmaf(sc[49], cq.x, conv);
        conv = fmaf(sc[50], cq.y, conv);

        // Pre-dot next window's top row (= this bottom row).
        atop = sc[42] * cm;
        atop = fmaf(sc[43], cq.x, atop);
        atop = fmaf(sc[44], cq.y, atop);

        // PReLU + affine + clamp -> exponent p
        float x = conv > 0.f ? conv : av * conv;
        float p = fminf(fmaxf(fmaf(x, wv, bv), 1.0f), 110.0f);

        // Power-mean over the 3x3 window (tree-summed ex2 burst).
        float t0 = f_ex2(p * ea)   + f_ex2(p * qa.x);
        float t1 = f_ex2(p * qa.y) + f_ex2(p * eb);
        float t2 = f_ex2(p * qb.x) + f_ex2(p * qb.y);
        float t3 = f_ex2(p * ec)   + f_ex2(p * qc.x);
        float sum = ((t0 + t1) + (t2 + t3)) + f_ex2(p * qc.y);

        float mean = fmaf(sum, (1.0f / 9.0f), 1e-12f);
        float res  = f_ex2(f_lg2(mean) * f_rcp(p));

        out_res[o] = res;
        out_p[o]   = p;

        // Shift: bottom row logs become next top row logs.
        ea = ec; qa = qc;
        srow += 2 * WW;
        ltr  += 2 * 65;
        o += WO;
    }
}

extern "C" void kernel_launch(void* const* d_in, const int* in_sizes, int n_in,
                              void* d_out, int out_size) {
    const float* bottom = (const float*)d_in[0];
    const float* w1     = (const float*)d_in[1];
    const float* a1     = (const float*)d_in[2];
    const float* w2     = (const float*)d_in[3];
    const float* b2     = (const float*)d_in[4];
    float* out = (float*)d_out;
    const size_t N = (size_t)BATCH * CH * HO * WO;   // elements per output tensor

    cudaFuncSetAttribute(fused_ppool_kernel,
                         cudaFuncAttributeMaxDynamicSharedMemorySize, SMEM_BYTES);

    dim3 blk(64, 16);
    fused_ppool_kernel<<<NPLANES, blk, SMEM_BYTES>>>(bottom, w1, a1, w2, b2,
                                                     out, out + N);

    (void)in_sizes; (void)n_in; (void)out_size;
}